// round 5
// baseline (speedup 1.0000x reference)
#include <cuda_runtime.h>
#include <math.h>

#define NQ 16
#define DIM 65536
#define BATCH 64
#define NPAIR 32
#define NC 23

typedef unsigned long long ull;

// state: per sample-pair p (samples 2p, 2p+1), per index: (reA, reB, imA, imB)
__device__ float4 g_st[NPAIR][DIM];              // 32 MB
__device__ ull    g_U2[2][NPAIR][NQ][8];         // packed U coeffs: r0,i0,r1,i1,r2,i2,r3,i3 (lanes A,B)
__device__ float2 g_crx[2][NQ];                  // (cos(th/2), sin(th/2)) -- batch independent
__device__ ull    g_part2[NPAIR][8][16];         // packed partial expvals

#define PD(i) ((i) + ((i) >> 4))
#define SMEM_F4 8704
#define SMEM_BYTES (SMEM_F4 * 16)

// ---- f32x2 packed primitives ------------------------------------------------
__device__ __forceinline__ ull pk(float a, float b) {
    ull r; asm("mov.b64 %0,{%1,%2};" : "=l"(r) : "f"(a), "f"(b)); return r;
}
__device__ __forceinline__ float2 upk(ull v) {
    float2 r; asm("mov.b64 {%0,%1},%2;" : "=f"(r.x), "=f"(r.y) : "l"(v)); return r;
}
__device__ __forceinline__ ull f2mul(ull a, ull b) {
    ull r; asm("mul.rn.f32x2 %0,%1,%2;" : "=l"(r) : "l"(a), "l"(b)); return r;
}
__device__ __forceinline__ ull f2fma(ull a, ull b, ull c) {
    ull r; asm("fma.rn.f32x2 %0,%1,%2,%3;" : "=l"(r) : "l"(a), "l"(b), "l"(c)); return r;
}
__device__ __forceinline__ ull f2add(ull a, ull b) {
    ull r; asm("add.rn.f32x2 %0,%1,%2;" : "=l"(r) : "l"(a), "l"(b)); return r;
}
__device__ __forceinline__ ull f2neg(ull a) { return a ^ 0x8000000080000000ULL; }

struct C2 { ull re, im; };
__device__ __forceinline__ C2 cmul2(C2 a, C2 b) {
    C2 o;
    o.re = f2fma(a.re, b.re, f2mul(f2neg(a.im), b.im));
    o.im = f2fma(a.re, b.im, f2mul(a.im, b.re));
    return o;
}
// CRX pair mix under control=1: RX=[[c,-is],[-is,c]]
__device__ __forceinline__ void crxmix2(C2& a0, C2& a1, ull c2, ull s2, ull ns2) {
    ull n0re = f2fma(c2, a0.re, f2mul(s2,  a1.im));
    ull n0im = f2fma(c2, a0.im, f2mul(ns2, a1.re));
    ull n1re = f2fma(c2, a1.re, f2mul(s2,  a0.im));
    ull n1im = f2fma(c2, a1.im, f2mul(ns2, a0.re));
    a0.re = n0re; a0.im = n0im; a1.re = n1re; a1.im = n1im;
}
struct UC { ull r0, i0, i0n, r1, i1, i1n, r2, i2, i2n, r3, i3, i3n; };
__device__ __forceinline__ UC loadUC(const ull* __restrict__ u) {
    UC c;
    c.r0 = u[0]; c.i0 = u[1]; c.r1 = u[2]; c.i1 = u[3];
    c.r2 = u[4]; c.i2 = u[5]; c.r3 = u[6]; c.i3 = u[7];
    c.i0n = f2neg(c.i0); c.i1n = f2neg(c.i1); c.i2n = f2neg(c.i2); c.i3n = f2neg(c.i3);
    return c;
}
__device__ __forceinline__ void umix2(C2& a0, C2& a1, const UC& u) {
    ull n0re = f2fma(u.r0, a0.re, f2fma(u.i0n, a0.im, f2fma(u.r1, a1.re, f2mul(u.i1n, a1.im))));
    ull n0im = f2fma(u.r0, a0.im, f2fma(u.i0,  a0.re, f2fma(u.r1, a1.im, f2mul(u.i1,  a1.re))));
    ull n1re = f2fma(u.r2, a0.re, f2fma(u.i2n, a0.im, f2fma(u.r3, a1.re, f2mul(u.i3n, a1.im))));
    ull n1im = f2fma(u.r2, a0.im, f2fma(u.i2,  a0.re, f2fma(u.r3, a1.im, f2mul(u.i3,  a1.re))));
    a0.re = n0re; a0.im = n0im; a1.re = n1re; a1.im = n1im;
}

// ---------------- P0: fused U = Rot @ RX (packed), CRX tables ----------------
__global__ void k_prep(const float* __restrict__ x, const float* __restrict__ w0,
                       const float* __restrict__ x0, const float* __restrict__ w1,
                       const float* __restrict__ x1) {
    int t = blockIdx.x * blockDim.x + threadIdx.x;
    if (t < 2 * NQ) {
        int l = t >> 4, q = t & 15;
        float th = 0.5f * (l == 0 ? x0[q] : x1[q]);
        g_crx[l][q] = make_float2(cosf(th), sinf(th));
    }
    if (t < 2 * BATCH * NQ) {
        int l = t / (BATCH * NQ);
        int r = t % (BATCH * NQ);
        int b = r / NQ, q = r % NQ;
        float hx = 0.5f * x[b * NQ + q];
        float cx = cosf(hx), sx = sinf(hx);
        const float* w = (l == 0 ? w0 : w1) + q * 3;
        float phi = w[0], th = w[1], om = w[2];
        float ct = cosf(0.5f * th), st = sinf(0.5f * th);
        float ap = 0.5f * (phi + om), am = 0.5f * (phi - om);
        float cap = cosf(ap), sap = sinf(ap), cam = cosf(am), sam = sinf(am);
        float2 a  = make_float2(cap * ct, -sap * ct);
        float2 bb = make_float2(-cam * st, -sam * st);
        float2 cc = make_float2(cam * st, -sam * st);
        float2 d  = make_float2(cap * ct,  sap * ct);
        float u[16];
        u[0] = a.x * cx + bb.y * sx;  u[1] = a.y * cx - bb.x * sx;   // U00
        u[2] = a.y * sx + bb.x * cx;  u[3] = -a.x * sx + bb.y * cx;  // U01
        u[4] = cc.x * cx + d.y * sx;  u[5] = cc.y * cx - d.x * sx;   // U10
        u[6] = cc.y * sx + d.x * cx;  u[7] = -cc.x * sx + d.y * cx;  // U11
        float* dst = (float*)&g_U2[l][b >> 1][q][0];
        int lane = b & 1;
        #pragma unroll
        for (int c = 0; c < 8; c++) dst[2 * c + lane] = u[c];
    }
}

// ------- P1: product state + L1 CRX q0 (b15->b14), q1 (b14->b13), q2 (b13->b12)
__global__ __launch_bounds__(512) void k_init() {
    int p = blockIdx.y;
    int t = blockIdx.x * blockDim.x + threadIdx.x;   // 0..4095 : bits 0..11
    __shared__ C2 f[16][2];
    if (threadIdx.x < 32) {
        int j = threadIdx.x >> 1, v = threadIdx.x & 1;
        const ull* u = &g_U2[0][p][15 - j][0];
        f[j][v].re = u[v ? 4 : 0];                   // column 0: u0 (v=0) / u2 (v=1)
        f[j][v].im = u[v ? 5 : 1];
    }
    __syncthreads();
    C2 c = f[0][t & 1];
    #pragma unroll
    for (int j = 1; j <= 11; j++) c = cmul2(c, f[j][(t >> j) & 1]);
    C2 t12[2], t13[4], t14[8], a[16];                // i = (b15<<3)|(b14<<2)|(b13<<1)|b12
    t12[0] = cmul2(c, f[12][0]); t12[1] = cmul2(c, f[12][1]);
    #pragma unroll
    for (int i = 0; i < 2; i++) { t13[i] = cmul2(t12[i], f[13][0]); t13[i + 2] = cmul2(t12[i], f[13][1]); }
    #pragma unroll
    for (int i = 0; i < 4; i++) { t14[i] = cmul2(t13[i], f[14][0]); t14[i + 4] = cmul2(t13[i], f[14][1]); }
    #pragma unroll
    for (int i = 0; i < 8; i++) { a[i] = cmul2(t14[i], f[15][0]); a[i + 8] = cmul2(t14[i], f[15][1]); }
    float2 cs = g_crx[0][0];                         // ctrl b15 -> tgt b14
    ull c2 = pk(cs.x, cs.x), s2 = pk(cs.y, cs.y), ns2 = f2neg(s2);
    #pragma unroll
    for (int i = 8; i < 12; i++) crxmix2(a[i], a[i | 4], c2, s2, ns2);
    cs = g_crx[0][1];                                // ctrl b14 -> tgt b13
    c2 = pk(cs.x, cs.x); s2 = pk(cs.y, cs.y); ns2 = f2neg(s2);
    crxmix2(a[4], a[6], c2, s2, ns2);   crxmix2(a[5], a[7], c2, s2, ns2);
    crxmix2(a[12], a[14], c2, s2, ns2); crxmix2(a[13], a[15], c2, s2, ns2);
    cs = g_crx[0][2];                                // ctrl b13 -> tgt b12
    c2 = pk(cs.x, cs.x); s2 = pk(cs.y, cs.y); ns2 = f2neg(s2);
    crxmix2(a[2], a[3], c2, s2, ns2);   crxmix2(a[6], a[7], c2, s2, ns2);
    crxmix2(a[10], a[11], c2, s2, ns2); crxmix2(a[14], a[15], c2, s2, ns2);
    float4* st = g_st[p];
    #pragma unroll
    for (int i = 0; i < 16; i++) {
        float2 re = upk(a[i].re), im = upk(a[i].im);
        st[(i << 12) | t] = make_float4(re.x, re.y, im.x, im.y);
    }
}

// ---------------- window gate helpers ----------------------------------------
template<int H, int L>
__device__ __forceinline__ void applyCRX2(C2* r, ull c2, ull s2, ull ns2) {
    #pragma unroll
    for (int j = 0; j < 16; j++)
        if (((j >> H) & 1) && !((j >> L) & 1))
            crxmix2(r[j], r[j | (1 << L)], c2, s2, ns2);
}
template<int K>
__device__ __forceinline__ void applyU2(C2* r, const ull* __restrict__ up) {
    UC u = loadUC(up);
    #pragma unroll
    for (int j = 0; j < 16; j++)
        if (!((j >> K) & 1))
            umix2(r[j], r[j | (1 << K)], u);
}

__device__ __forceinline__ void window_pass2(float4* s4, const ull (*sU)[8],
                                             int tid, int sh, bool dou, int layer) {
    int low  = tid & ((1 << sh) - 1);
    int base = ((tid >> sh) << (sh + 4)) | low;
    C2 r[16];
    #pragma unroll
    for (int j = 0; j < 16; j++) {
        float4 v = s4[PD(base + (j << sh))];
        r[j].re = pk(v.x, v.y); r[j].im = pk(v.z, v.w);
    }
    {
        float2 cs = g_crx[layer][12 - sh];
        ull c2 = pk(cs.x, cs.x), s2 = pk(cs.y, cs.y);
        applyCRX2<3, 2>(r, c2, s2, f2neg(s2));
    }
    {
        float2 cs = g_crx[layer][13 - sh];
        ull c2 = pk(cs.x, cs.x), s2 = pk(cs.y, cs.y);
        applyCRX2<2, 1>(r, c2, s2, f2neg(s2));
    }
    {
        float2 cs = g_crx[layer][14 - sh];
        ull c2 = pk(cs.x, cs.x), s2 = pk(cs.y, cs.y);
        applyCRX2<1, 0>(r, c2, s2, f2neg(s2));
    }
    if (dou) {
        applyU2<3>(r, sU[12 - sh]);
        applyU2<2>(r, sU[13 - sh]);
        applyU2<1>(r, sU[14 - sh]);
    }
    #pragma unroll
    for (int j = 0; j < 16; j++) {
        float2 re = upk(r[j].re), im = upk(r[j].im);
        s4[PD(base + (j << sh))] = make_float4(re.x, re.y, im.x, im.y);
    }
}

// ------- P2/P4: 128KB chunk (bits 0..12), 4 window passes --------------------
__global__ __launch_bounds__(512) void k_chain(int layer) {
    extern __shared__ float4 s4[];
    __shared__ ull sU[16][8];
    int p = blockIdx.y, tid = threadIdx.x;
    float4* g = g_st[p] + (size_t)blockIdx.x * 8192;
    bool dou = (layer == 0);
    if (tid < 128) sU[tid >> 3][tid & 7] = g_U2[1][p][tid >> 3][tid & 7];
    #pragma unroll
    for (int k = 0; k < 16; k++) {
        int q = tid + (k << 9);
        s4[PD(q)] = g[q];
    }
    __syncthreads();
    window_pass2(s4, sU, tid, 9, dou, layer); __syncthreads();
    window_pass2(s4, sU, tid, 6, dou, layer); __syncthreads();
    window_pass2(s4, sU, tid, 3, dou, layer); __syncthreads();
    window_pass2(s4, sU, tid, 0, dou, layer); __syncthreads();
    #pragma unroll
    for (int k = 0; k < 16; k++) {
        int q = tid + (k << 9);
        g[q] = s4[PD(q)];
    }
}

// ------- P3: boundary gates on bits {15,14,13,12,0} --------------------------
// L1 wrap q15; L2 U wires 0,1,2,15; L2 CRX q0,q1,q2.
__global__ __launch_bounds__(128) void k_boundary() {
    int p = blockIdx.y;
    int t = blockIdx.x * blockDim.x + threadIdx.x;   // 0..2047 : bits 1..11
    float4* g = g_st[p];
    C2 r[16][2];                                     // [i=(b15<<3)|(b14<<2)|(b13<<1)|b12][b0]
    #pragma unroll
    for (int i = 0; i < 16; i++)
        #pragma unroll
        for (int b0 = 0; b0 < 2; b0++) {
            float4 v = g[(i << 12) | (t << 1) | b0];
            r[i][b0].re = pk(v.x, v.y); r[i][b0].im = pk(v.z, v.w);
        }
    {   // L1 wrap: ctrl b0 -> tgt b15
        float2 cs = g_crx[0][15];
        ull c2 = pk(cs.x, cs.x), s2 = pk(cs.y, cs.y), ns2 = f2neg(s2);
        #pragma unroll
        for (int i = 0; i < 8; i++) crxmix2(r[i][1], r[i + 8][1], c2, s2, ns2);
    }
    {   // L2 U wire 0 (bit 15)
        UC u = loadUC(&g_U2[1][p][0][0]);
        #pragma unroll
        for (int i = 0; i < 8; i++) {
            umix2(r[i][0], r[i + 8][0], u);
            umix2(r[i][1], r[i + 8][1], u);
        }
    }
    {   // L2 U wire 1 (bit 14)
        UC u = loadUC(&g_U2[1][p][1][0]);
        #pragma unroll
        for (int i = 0; i < 16; i++)
            if (!((i >> 2) & 1)) { umix2(r[i][0], r[i + 4][0], u); umix2(r[i][1], r[i + 4][1], u); }
    }
    {   // L2 U wire 2 (bit 13)
        UC u = loadUC(&g_U2[1][p][2][0]);
        #pragma unroll
        for (int i = 0; i < 16; i++)
            if (!((i >> 1) & 1)) { umix2(r[i][0], r[i + 2][0], u); umix2(r[i][1], r[i + 2][1], u); }
    }
    {   // L2 U wire 15 (bit 0)
        UC u = loadUC(&g_U2[1][p][15][0]);
        #pragma unroll
        for (int i = 0; i < 16; i++) umix2(r[i][0], r[i][1], u);
    }
    {   // L2 q0: ctrl b15 -> tgt b14
        float2 cs = g_crx[1][0];
        ull c2 = pk(cs.x, cs.x), s2 = pk(cs.y, cs.y), ns2 = f2neg(s2);
        #pragma unroll
        for (int i = 8; i < 12; i++) {
            crxmix2(r[i][0], r[i + 4][0], c2, s2, ns2);
            crxmix2(r[i][1], r[i + 4][1], c2, s2, ns2);
        }
    }
    {   // L2 q1: ctrl b14 -> tgt b13
        float2 cs = g_crx[1][1];
        ull c2 = pk(cs.x, cs.x), s2 = pk(cs.y, cs.y), ns2 = f2neg(s2);
        #pragma unroll
        for (int i = 0; i < 16; i++)
            if (((i >> 2) & 1) && !((i >> 1) & 1)) {
                crxmix2(r[i][0], r[i + 2][0], c2, s2, ns2);
                crxmix2(r[i][1], r[i + 2][1], c2, s2, ns2);
            }
    }
    {   // L2 q2: ctrl b13 -> tgt b12
        float2 cs = g_crx[1][2];
        ull c2 = pk(cs.x, cs.x), s2 = pk(cs.y, cs.y), ns2 = f2neg(s2);
        #pragma unroll
        for (int i = 0; i < 16; i++)
            if (((i >> 1) & 1) && !(i & 1)) {
                crxmix2(r[i][0], r[i + 1][0], c2, s2, ns2);
                crxmix2(r[i][1], r[i + 1][1], c2, s2, ns2);
            }
    }
    #pragma unroll
    for (int i = 0; i < 16; i++)
        #pragma unroll
        for (int b0 = 0; b0 < 2; b0++) {
            float2 re = upk(r[i][b0].re), im = upk(r[i][b0].im);
            g[(i << 12) | (t << 1) | b0] = make_float4(re.x, re.y, im.x, im.y);
        }
}

// ------- P5: final L2 wrap CRX (q15: b0->b15) + signed |amp|^2 reduction -----
__global__ __launch_bounds__(256) void k_measure() {
    int p = blockIdx.y, blk = blockIdx.x, tid = threadIdx.x;
    const float4* st = g_st[p];
    float2 csw = g_crx[1][15];
    ull c2 = pk(csw.x, csw.x), s2 = pk(csw.y, csw.y), ns2 = f2neg(s2);
    ull sums[16];
    #pragma unroll
    for (int w = 0; w < 16; w++) sums[w] = 0ULL;
    #pragma unroll
    for (int k = 0; k < 8; k++) {
        int u = blk * 2048 + tid + k * 256;          // pair-of-j index, 0..16383
        int j0 = u << 1;
        float4 v;
        C2 a0lo, a0hi, a1lo, a1hi;
        v = st[j0];           a0lo.re = pk(v.x, v.y); a0lo.im = pk(v.z, v.w);
        v = st[j0 + 1];       a1lo.re = pk(v.x, v.y); a1lo.im = pk(v.z, v.w);
        v = st[j0 + 32768];   a0hi.re = pk(v.x, v.y); a0hi.im = pk(v.z, v.w);
        v = st[j0 + 32769];   a1hi.re = pk(v.x, v.y); a1hi.im = pk(v.z, v.w);
        crxmix2(a1lo, a1hi, c2, s2, ns2);            // wrap only on odd j (b0=1)
        ull p0lo = f2fma(a0lo.re, a0lo.re, f2mul(a0lo.im, a0lo.im));
        ull p0hi = f2fma(a0hi.re, a0hi.re, f2mul(a0hi.im, a0hi.im));
        ull p1lo = f2fma(a1lo.re, a1lo.re, f2mul(a1lo.im, a1lo.im));
        ull p1hi = f2fma(a1hi.re, a1hi.re, f2mul(a1hi.im, a1hi.im));
        // wire 0 = bit 15
        sums[0] = f2add(sums[0], f2add(f2add(p0lo, f2neg(p0hi)), f2add(p1lo, f2neg(p1hi))));
        // wire 15 = bit 0
        sums[15] = f2add(sums[15], f2add(f2add(p0lo, p0hi), f2neg(f2add(p1lo, p1hi))));
        ull sboth = f2add(f2add(p0lo, p0hi), f2add(p1lo, p1hi));
        #pragma unroll
        for (int w = 1; w < 15; w++) {
            ull msk = ((j0 >> (15 - w)) & 1) ? 0x8000000080000000ULL : 0ULL;
            sums[w] = f2add(sums[w], sboth ^ msk);
        }
    }
    __shared__ ull sm[256][16];
    #pragma unroll
    for (int w = 0; w < 16; w++) sm[tid][w] = sums[w];
    __syncthreads();
    if (tid < 16) {
        ull v = 0ULL;
        for (int i = 0; i < 256; i++) v = f2add(v, sm[i][tid]);
        g_part2[p][blk][tid] = v;
    }
}

// ---------------- P6: FC + log_softmax --------------------------------------
__global__ void k_head(const float* __restrict__ fc_w, const float* __restrict__ fc_b,
                       float* __restrict__ out) {
    int b = blockIdx.x, lane = threadIdx.x;
    int p = b >> 1, ln = b & 1;
    __shared__ float feats[16];
    if (lane < 16) {
        float v = 0.f;
        const float* src = (const float*)&g_part2[p][0][0];
        #pragma unroll
        for (int k = 0; k < 8; k++) v += src[(k * 16 + lane) * 2 + ln];
        feats[lane] = v;
    }
    __syncthreads();
    float logit = -1e30f;
    if (lane < NC) {
        float v = fc_b[lane];
        #pragma unroll
        for (int w = 0; w < 16; w++) v += feats[w] * fc_w[lane * 16 + w];
        logit = v;
    }
    float m = logit;
    #pragma unroll
    for (int o = 16; o; o >>= 1) m = fmaxf(m, __shfl_xor_sync(0xffffffffu, m, o));
    float e = (lane < NC) ? expf(logit - m) : 0.f;
    #pragma unroll
    for (int o = 16; o; o >>= 1) e += __shfl_xor_sync(0xffffffffu, e, o);
    float lse = m + logf(e);
    if (lane < NC) out[b * NC + lane] = logit - lse;
}

extern "C" void kernel_launch(void* const* d_in, const int* in_sizes, int n_in,
                              void* d_out, int out_size) {
    const float* x    = (const float*)d_in[0];
    const float* w0   = (const float*)d_in[1];
    const float* x0   = (const float*)d_in[2];
    const float* w1   = (const float*)d_in[3];
    const float* x1   = (const float*)d_in[4];
    const float* fc_w = (const float*)d_in[5];
    const float* fc_b = (const float*)d_in[6];
    float* out = (float*)d_out;

    cudaFuncSetAttribute(k_chain, cudaFuncAttributeMaxDynamicSharedMemorySize, SMEM_BYTES);

    k_prep<<<8, 256>>>(x, w0, x0, w1, x1);
    k_init<<<dim3(8, NPAIR), 512>>>();
    k_chain<<<dim3(8, NPAIR), 512, SMEM_BYTES>>>(0);
    k_boundary<<<dim3(16, NPAIR), 128>>>();
    k_chain<<<dim3(8, NPAIR), 512, SMEM_BYTES>>>(1);
    k_measure<<<dim3(8, NPAIR), 256>>>();
    k_head<<<BATCH, 32>>>(fc_w, fc_b, out);
}

// round 6
// speedup vs baseline: 1.0221x; 1.0221x over previous
#include <cuda_runtime.h>
#include <math.h>

#define NQ 16
#define DIM 65536
#define BATCH 64
#define NC 23

__device__ float4 g_state4[BATCH * DIM / 2];   // 32 MB state
__device__ float2 g_U[2][BATCH][NQ][4];        // fused Rot@RX per layer/sample/wire
__device__ float2 g_crx[2][NQ];                // (cos(th/2), sin(th/2))
__device__ float  g_partial[BATCH][8][16];

// smem pad (float2 index): <=2-way conflicts on all window strides
#define PD(i) ((i) + ((i) >> 4))
#define SMEM_F2 8704
#define SMEM_BYTES (SMEM_F2 * 8)

__device__ __forceinline__ float2 cmul(float2 a, float2 b) {
    return make_float2(a.x * b.x - a.y * b.y, a.x * b.y + a.y * b.x);
}
__device__ __forceinline__ void umix(float2& a0, float2& a1,
                                     float2 u0, float2 u1, float2 u2, float2 u3) {
    float2 n0, n1;
    n0.x = u0.x * a0.x - u0.y * a0.y + u1.x * a1.x - u1.y * a1.y;
    n0.y = u0.x * a0.y + u0.y * a0.x + u1.x * a1.y + u1.y * a1.x;
    n1.x = u2.x * a0.x - u2.y * a0.y + u3.x * a1.x - u3.y * a1.y;
    n1.y = u2.x * a0.y + u2.y * a0.x + u3.x * a1.y + u3.y * a1.x;
    a0 = n0; a1 = n1;
}
// RX pair mix applied under control=1: RX=[[c,-is],[-is,c]]
__device__ __forceinline__ void crxmix(float2& a0, float2& a1, float c, float s) {
    float2 n0 = make_float2(c * a0.x + s * a1.y, c * a0.y - s * a1.x);
    float2 n1 = make_float2(s * a0.y + c * a1.x, -s * a0.x + c * a1.y);
    a0 = n0; a1 = n1;
}

// ---------------- P0: fused U = Rot @ RX, CRX tables ------------------------
__global__ void k_prep(const float* __restrict__ x, const float* __restrict__ w0,
                       const float* __restrict__ x0, const float* __restrict__ w1,
                       const float* __restrict__ x1) {
    int t = blockIdx.x * blockDim.x + threadIdx.x;
    if (t < 2 * NQ) {
        int l = t >> 4, q = t & 15;
        float th = 0.5f * (l == 0 ? x0[q] : x1[q]);
        g_crx[l][q] = make_float2(cosf(th), sinf(th));
    }
    if (t < 2 * BATCH * NQ) {
        int l = t / (BATCH * NQ);
        int r = t % (BATCH * NQ);
        int b = r / NQ, q = r % NQ;
        float hx = 0.5f * x[b * NQ + q];
        float cx = cosf(hx), sx = sinf(hx);
        const float* w = (l == 0 ? w0 : w1) + q * 3;
        float phi = w[0], th = w[1], om = w[2];
        float ct = cosf(0.5f * th), st = sinf(0.5f * th);
        float ap = 0.5f * (phi + om), am = 0.5f * (phi - om);
        float cap = cosf(ap), sap = sinf(ap), cam = cosf(am), sam = sinf(am);
        float2 a  = make_float2(cap * ct, -sap * ct);
        float2 bb = make_float2(-cam * st, -sam * st);
        float2 cc = make_float2(cam * st, -sam * st);
        float2 d  = make_float2(cap * ct,  sap * ct);
        g_U[l][b][q][0] = make_float2(a.x * cx + bb.y * sx,  a.y * cx - bb.x * sx);
        g_U[l][b][q][1] = make_float2(a.y * sx + bb.x * cx, -a.x * sx + bb.y * cx);
        g_U[l][b][q][2] = make_float2(cc.x * cx + d.y * sx,  cc.y * cx - d.x * sx);
        g_U[l][b][q][3] = make_float2(cc.y * sx + d.x * cx, -cc.x * sx + d.y * cx);
    }
}

// ------- P1: product state + L1 CRX q0 (b15->b14), q1 (b14->b13) -------------
__global__ __launch_bounds__(512) void k_init() {
    int b = blockIdx.y;
    int t = blockIdx.x * blockDim.x + threadIdx.x;   // 0..8191 : bits 0..12
    __shared__ float2 f[16][2];
    if (threadIdx.x < 32) {
        int j = threadIdx.x >> 1, v = threadIdx.x & 1;
        f[j][v] = g_U[0][b][15 - j][v * 2];          // column 0 of U, wire 15-j
    }
    __syncthreads();
    float2 c = f[0][t & 1];
    #pragma unroll
    for (int j = 1; j <= 12; j++) c = cmul(c, f[j][(t >> j) & 1]);
    float2 t13[2], t14[4], a[8];                     // i = (b15<<2)|(b14<<1)|b13
    t13[0] = cmul(c, f[13][0]); t13[1] = cmul(c, f[13][1]);
    #pragma unroll
    for (int i = 0; i < 2; i++) { t14[i] = cmul(t13[i], f[14][0]); t14[i + 2] = cmul(t13[i], f[14][1]); }
    #pragma unroll
    for (int i = 0; i < 4; i++) { a[i] = cmul(t14[i], f[15][0]); a[i + 4] = cmul(t14[i], f[15][1]); }
    float2 cs = g_crx[0][0];                         // q0: ctrl b15 -> tgt b14
    crxmix(a[4], a[6], cs.x, cs.y); crxmix(a[5], a[7], cs.x, cs.y);
    cs = g_crx[0][1];                                // q1: ctrl b14 -> tgt b13
    crxmix(a[2], a[3], cs.x, cs.y); crxmix(a[6], a[7], cs.x, cs.y);
    float2* st = (float2*)g_state4 + (size_t)b * DIM;
    #pragma unroll
    for (int i = 0; i < 8; i++) st[(i << 13) | t] = a[i];
}

// ---------------- window gate helpers ----------------------------------------
template<int H, int L>
__device__ __forceinline__ void applyCRX(float2* r, float2 cs) {
    #pragma unroll
    for (int j = 0; j < 16; j++)
        if (((j >> H) & 1) && !((j >> L) & 1))
            crxmix(r[j], r[j | (1 << L)], cs.x, cs.y);
}
template<int K>
__device__ __forceinline__ void applyU(float2* r, const float2* __restrict__ gu) {
    float2 u0 = gu[0], u1 = gu[1], u2 = gu[2], u3 = gu[3];
    #pragma unroll
    for (int j = 0; j < 16; j++)
        if (!((j >> K) & 1))
            umix(r[j], r[j | (1 << K)], u0, u1, u2, u3);
}

// one 4-bit window over bits [sh, sh+3]; CRX q = 12-sh,13-sh,14-sh (+ cond q2 RX
// on bit sh+3 when first window & chunk bit13==1); if dou, L2 U wires 12..14-sh.
__device__ __forceinline__ void window_pass(float2* s, int tid, int b, int sh,
                                            bool dou, int layer, bool doq2) {
    int low  = tid & ((1 << sh) - 1);
    int base = ((tid >> sh) << (sh + 4)) | low;
    float2 r[16];
    #pragma unroll
    for (int j = 0; j < 16; j++) r[j] = s[PD(base + (j << sh))];
    if (doq2) {                                       // q2 RX on bit sh+3 (=12)
        float2 cs = g_crx[layer][2];
        #pragma unroll
        for (int j = 0; j < 8; j++) crxmix(r[j], r[j | 8], cs.x, cs.y);
    }
    applyCRX<3, 2>(r, g_crx[layer][12 - sh]);
    applyCRX<2, 1>(r, g_crx[layer][13 - sh]);
    applyCRX<1, 0>(r, g_crx[layer][14 - sh]);
    if (dou) {
        applyU<3>(r, &g_U[1][b][12 - sh][0]);
        applyU<2>(r, &g_U[1][b][13 - sh][0]);
        applyU<1>(r, &g_U[1][b][14 - sh][0]);
    }
    #pragma unroll
    for (int j = 0; j < 16; j++) s[PD(base + (j << sh))] = r[j];
}

// ------- P2/P4: 64KB chunk (bits 0..12), 4 window passes ---------------------
// layer 0: L1 CRX q2(cond)..q14 + L2 U wires 3..14.  layer 1: L2 CRX q2(cond)..q14.
__global__ __launch_bounds__(512, 2) void k_chain(int layer) {
    extern __shared__ float2 s[];
    int b = blockIdx.y, tid = threadIdx.x;
    float4* g4 = g_state4 + (size_t)b * 32768 + (size_t)blockIdx.x * 4096;
    bool dou = (layer == 0);
    bool doq2 = (blockIdx.x & 1);                    // chunk bit13 == 1
    #pragma unroll
    for (int k = 0; k < 8; k++) {
        int p = tid + (k << 9);
        float4 v = g4[p];
        s[PD(2 * p)]     = make_float2(v.x, v.y);
        s[PD(2 * p + 1)] = make_float2(v.z, v.w);
    }
    __syncthreads();
    window_pass(s, tid, b, 9, dou, layer, doq2); __syncthreads();
    window_pass(s, tid, b, 6, dou, layer, false); __syncthreads();
    window_pass(s, tid, b, 3, dou, layer, false); __syncthreads();
    window_pass(s, tid, b, 0, dou, layer, false); __syncthreads();
    #pragma unroll
    for (int k = 0; k < 8; k++) {
        int p = tid + (k << 9);
        float2 lo = s[PD(2 * p)], hi = s[PD(2 * p + 1)];
        g4[p] = make_float4(lo.x, lo.y, hi.x, hi.y);
    }
}

// ------- P3: boundary gates on bits {15,14,13,0} -----------------------------
// L1 wrap q15; L2 U wires 0,1,2,15; L2 CRX q0,q1.
__global__ __launch_bounds__(256, 4) void k_boundary() {
    int b = blockIdx.y;
    int t = blockIdx.x * blockDim.x + threadIdx.x;   // 0..4095 : f4 idx bits 0..11 (j bits 1..12)
    float4* g4 = g_state4 + (size_t)b * 32768;
    float2 r[8][2];                                  // [i=(b15<<2)|(b14<<1)|b13][b0]
    #pragma unroll
    for (int i = 0; i < 8; i++) {
        float4 v = g4[(i << 12) | t];
        r[i][0] = make_float2(v.x, v.y);
        r[i][1] = make_float2(v.z, v.w);
    }
    {   // L1 wrap q15: ctrl b0 -> tgt b15
        float2 cs = g_crx[0][15];
        #pragma unroll
        for (int i = 0; i < 4; i++) crxmix(r[i][1], r[i + 4][1], cs.x, cs.y);
    }
    {   // L2 U wire 0 (bit 15)
        const float2* gu = &g_U[1][b][0][0];
        float2 u0 = gu[0], u1 = gu[1], u2 = gu[2], u3 = gu[3];
        #pragma unroll
        for (int i = 0; i < 4; i++) {
            umix(r[i][0], r[i + 4][0], u0, u1, u2, u3);
            umix(r[i][1], r[i + 4][1], u0, u1, u2, u3);
        }
    }
    {   // L2 U wire 1 (bit 14)
        const float2* gu = &g_U[1][b][1][0];
        float2 u0 = gu[0], u1 = gu[1], u2 = gu[2], u3 = gu[3];
        #pragma unroll
        for (int i = 0; i < 8; i++)
            if (!((i >> 1) & 1)) {
                umix(r[i][0], r[i + 2][0], u0, u1, u2, u3);
                umix(r[i][1], r[i + 2][1], u0, u1, u2, u3);
            }
    }
    {   // L2 U wire 2 (bit 13)
        const float2* gu = &g_U[1][b][2][0];
        float2 u0 = gu[0], u1 = gu[1], u2 = gu[2], u3 = gu[3];
        #pragma unroll
        for (int i = 0; i < 8; i += 2) {
            umix(r[i][0], r[i + 1][0], u0, u1, u2, u3);
            umix(r[i][1], r[i + 1][1], u0, u1, u2, u3);
        }
    }
    {   // L2 U wire 15 (bit 0)
        const float2* gu = &g_U[1][b][15][0];
        float2 u0 = gu[0], u1 = gu[1], u2 = gu[2], u3 = gu[3];
        #pragma unroll
        for (int i = 0; i < 8; i++)
            umix(r[i][0], r[i][1], u0, u1, u2, u3);
    }
    {   // L2 q0: ctrl b15 -> tgt b14
        float2 cs = g_crx[1][0];
        #pragma unroll
        for (int b0 = 0; b0 < 2; b0++) {
            crxmix(r[4][b0], r[6][b0], cs.x, cs.y);
            crxmix(r[5][b0], r[7][b0], cs.x, cs.y);
        }
    }
    {   // L2 q1: ctrl b14 -> tgt b13
        float2 cs = g_crx[1][1];
        #pragma unroll
        for (int b0 = 0; b0 < 2; b0++) {
            crxmix(r[2][b0], r[3][b0], cs.x, cs.y);
            crxmix(r[6][b0], r[7][b0], cs.x, cs.y);
        }
    }
    #pragma unroll
    for (int i = 0; i < 8; i++)
        g4[(i << 12) | t] = make_float4(r[i][0].x, r[i][0].y, r[i][1].x, r[i][1].y);
}

// ------- P5: final L2 wrap CRX (q15: b0->b15) + signed |amp|^2 reduction -----
__global__ __launch_bounds__(256, 4) void k_measure() {
    int b = blockIdx.y, blk = blockIdx.x, tid = threadIdx.x;
    const float4* st4 = g_state4 + (size_t)b * 32768;
    float2 cs = g_crx[1][15];
    float sums[16];
    #pragma unroll
    for (int w = 0; w < 16; w++) sums[w] = 0.f;
    #pragma unroll
    for (int k = 0; k < 8; k++) {
        int f = blk * 2048 + tid + k * 256;          // f4 idx: j bits 1..14
        float4 lo = st4[f], hi = st4[f + 16384];
        float2 a0e = make_float2(lo.x, lo.y), a0o = make_float2(lo.z, lo.w);
        float2 a1e = make_float2(hi.x, hi.y), a1o = make_float2(hi.z, hi.w);
        crxmix(a0o, a1o, cs.x, cs.y);                // wrap only where bit0=1
        float p0e = a0e.x * a0e.x + a0e.y * a0e.y;
        float p1e = a1e.x * a1e.x + a1e.y * a1e.y;
        float p0o = a0o.x * a0o.x + a0o.y * a0o.y;
        float p1o = a1o.x * a1o.x + a1o.y * a1o.y;
        int j = f << 1;
        sums[0] += (p0e - p1e) + (p0o - p1o);        // wire 0 = bit 15
        float se = p0e + p1e, so = p0o + p1o;
        float sall = se + so;
        #pragma unroll
        for (int w = 1; w < 15; w++)
            sums[w] += ((j >> (15 - w)) & 1) ? -sall : sall;
        sums[15] += se - so;                         // wire 15 = bit 0
    }
    __shared__ float sm[256][16];
    #pragma unroll
    for (int w = 0; w < 16; w++) sm[tid][w] = sums[w];
    __syncthreads();
    if (tid < 16) {
        float v = 0.f;
        for (int i = 0; i < 256; i++) v += sm[i][tid];
        g_partial[b][blk][tid] = v;
    }
}

// ---------------- P6: FC + log_softmax --------------------------------------
__global__ void k_head(const float* __restrict__ fc_w, const float* __restrict__ fc_b,
                       float* __restrict__ out) {
    int b = blockIdx.x, lane = threadIdx.x;
    __shared__ float feats[16];
    if (lane < 16) {
        float v = 0.f;
        #pragma unroll
        for (int k = 0; k < 8; k++) v += g_partial[b][k][lane];
        feats[lane] = v;
    }
    __syncthreads();
    float logit = -1e30f;
    if (lane < NC) {
        float v = fc_b[lane];
        #pragma unroll
        for (int w = 0; w < 16; w++) v += feats[w] * fc_w[lane * 16 + w];
        logit = v;
    }
    float m = logit;
    #pragma unroll
    for (int o = 16; o; o >>= 1) m = fmaxf(m, __shfl_xor_sync(0xffffffffu, m, o));
    float e = (lane < NC) ? expf(logit - m) : 0.f;
    #pragma unroll
    for (int o = 16; o; o >>= 1) e += __shfl_xor_sync(0xffffffffu, e, o);
    float lse = m + logf(e);
    if (lane < NC) out[b * NC + lane] = logit - lse;
}

extern "C" void kernel_launch(void* const* d_in, const int* in_sizes, int n_in,
                              void* d_out, int out_size) {
    const float* x    = (const float*)d_in[0];
    const float* w0   = (const float*)d_in[1];
    const float* x0   = (const float*)d_in[2];
    const float* w1   = (const float*)d_in[3];
    const float* x1   = (const float*)d_in[4];
    const float* fc_w = (const float*)d_in[5];
    const float* fc_b = (const float*)d_in[6];
    float* out = (float*)d_out;

    cudaFuncSetAttribute(k_chain, cudaFuncAttributeMaxDynamicSharedMemorySize, SMEM_BYTES);

    k_prep<<<8, 256>>>(x, w0, x0, w1, x1);
    k_init<<<dim3(16, BATCH), 512>>>();
    k_chain<<<dim3(8, BATCH), 512, SMEM_BYTES>>>(0);
    k_boundary<<<dim3(16, BATCH), 256>>>();
    k_chain<<<dim3(8, BATCH), 512, SMEM_BYTES>>>(1);
    k_measure<<<dim3(8, BATCH), 256>>>();
    k_head<<<BATCH, 32>>>(fc_w, fc_b, out);
}

// round 7
// speedup vs baseline: 1.1982x; 1.1724x over previous
#include <cuda_runtime.h>
#include <math.h>

#define NQ 16
#define DIM 65536
#define BATCH 64
#define NC 23

__device__ float4 g_state4[BATCH * DIM / 2];   // 32 MB state
__device__ float2 g_U[2][BATCH][NQ][4];        // fused Rot@RX per layer/sample/wire
__device__ float2 g_crx[2][NQ];                // (cos(th/2), sin(th/2))
__device__ float  g_partial[BATCH][8][16];

// smem pad (float2 index): <=2-way conflicts on all window strides
#define PD(i) ((i) + ((i) >> 4))
#define SMEM_F2 8704
#define SMEM_BYTES (SMEM_F2 * 8)

__device__ __forceinline__ float2 cmul(float2 a, float2 b) {
    return make_float2(a.x * b.x - a.y * b.y, a.x * b.y + a.y * b.x);
}
__device__ __forceinline__ void umix(float2& a0, float2& a1,
                                     float2 u0, float2 u1, float2 u2, float2 u3) {
    float2 n0, n1;
    n0.x = u0.x * a0.x - u0.y * a0.y + u1.x * a1.x - u1.y * a1.y;
    n0.y = u0.x * a0.y + u0.y * a0.x + u1.x * a1.y + u1.y * a1.x;
    n1.x = u2.x * a0.x - u2.y * a0.y + u3.x * a1.x - u3.y * a1.y;
    n1.y = u2.x * a0.y + u2.y * a0.x + u3.x * a1.y + u3.y * a1.x;
    a0 = n0; a1 = n1;
}
// RX pair mix applied under control=1: RX=[[c,-is],[-is,c]]
__device__ __forceinline__ void crxmix(float2& a0, float2& a1, float c, float s) {
    float2 n0 = make_float2(c * a0.x + s * a1.y, c * a0.y - s * a1.x);
    float2 n1 = make_float2(s * a0.y + c * a1.x, -s * a0.x + c * a1.y);
    a0 = n0; a1 = n1;
}

// ---------------- P0: fused U = Rot @ RX, CRX tables ------------------------
__global__ void k_prep(const float* __restrict__ x, const float* __restrict__ w0,
                       const float* __restrict__ x0, const float* __restrict__ w1,
                       const float* __restrict__ x1) {
    int t = blockIdx.x * blockDim.x + threadIdx.x;
    if (t < 2 * NQ) {
        int l = t >> 4, q = t & 15;
        float th = 0.5f * (l == 0 ? x0[q] : x1[q]);
        g_crx[l][q] = make_float2(cosf(th), sinf(th));
    }
    if (t < 2 * BATCH * NQ) {
        int l = t / (BATCH * NQ);
        int r = t % (BATCH * NQ);
        int b = r / NQ, q = r % NQ;
        float hx = 0.5f * x[b * NQ + q];
        float cx = cosf(hx), sx = sinf(hx);
        const float* w = (l == 0 ? w0 : w1) + q * 3;
        float phi = w[0], th = w[1], om = w[2];
        float ct = cosf(0.5f * th), st = sinf(0.5f * th);
        float ap = 0.5f * (phi + om), am = 0.5f * (phi - om);
        float cap = cosf(ap), sap = sinf(ap), cam = cosf(am), sam = sinf(am);
        float2 a  = make_float2(cap * ct, -sap * ct);
        float2 bb = make_float2(-cam * st, -sam * st);
        float2 cc = make_float2(cam * st, -sam * st);
        float2 d  = make_float2(cap * ct,  sap * ct);
        g_U[l][b][q][0] = make_float2(a.x * cx + bb.y * sx,  a.y * cx - bb.x * sx);
        g_U[l][b][q][1] = make_float2(a.y * sx + bb.x * cx, -a.x * sx + bb.y * cx);
        g_U[l][b][q][2] = make_float2(cc.x * cx + d.y * sx,  cc.y * cx - d.x * sx);
        g_U[l][b][q][3] = make_float2(cc.y * sx + d.x * cx, -cc.x * sx + d.y * cx);
    }
}

// ---------------- window gate helpers ----------------------------------------
template<int H, int L>
__device__ __forceinline__ void applyCRX(float2* r, float2 cs) {
    #pragma unroll
    for (int j = 0; j < 16; j++)
        if (((j >> H) & 1) && !((j >> L) & 1))
            crxmix(r[j], r[j | (1 << L)], cs.x, cs.y);
}
template<int K>
__device__ __forceinline__ void applyU(float2* r, const float2* __restrict__ gu) {
    float2 u0 = gu[0], u1 = gu[1], u2 = gu[2], u3 = gu[3];
    #pragma unroll
    for (int j = 0; j < 16; j++)
        if (!((j >> K) & 1))
            umix(r[j], r[j | (1 << K)], u0, u1, u2, u3);
}

// one 4-bit window instance over bits [sh, sh+3]; CRX q = 12-sh,13-sh,14-sh
// (+ cond q2 RX on bit 12 when sh==9 & chunk bit13==1); if dou, L2 U wires.
__device__ __forceinline__ void window_one(float2* s, int wid, int b, int sh,
                                           bool dou, int layer, bool doq2) {
    int low  = wid & ((1 << sh) - 1);
    int base = ((wid >> sh) << (sh + 4)) | low;
    float2 r[16];
    #pragma unroll
    for (int j = 0; j < 16; j++) r[j] = s[PD(base + (j << sh))];
    if (doq2) {                                       // q2 RX on window bit 3 (=abs 12)
        float2 cs = g_crx[layer][2];
        #pragma unroll
        for (int j = 0; j < 8; j++) crxmix(r[j], r[j | 8], cs.x, cs.y);
    }
    applyCRX<3, 2>(r, g_crx[layer][12 - sh]);
    applyCRX<2, 1>(r, g_crx[layer][13 - sh]);
    applyCRX<1, 0>(r, g_crx[layer][14 - sh]);
    if (dou) {
        applyU<3>(r, &g_U[1][b][12 - sh][0]);
        applyU<2>(r, &g_U[1][b][13 - sh][0]);
        applyU<1>(r, &g_U[1][b][14 - sh][0]);
    }
    #pragma unroll
    for (int j = 0; j < 16; j++) s[PD(base + (j << sh))] = r[j];
}
__device__ __forceinline__ void window_pass(float2* s, int tid, int b, int sh,
                                            bool dou, int layer, bool doq2) {
    window_one(s, tid,       b, sh, dou, layer, doq2);
    window_one(s, tid + 256, b, sh, dou, layer, doq2);
}

// ------- P1/P3: 64KB chunk (bits 0..12), 4 window passes ---------------------
// layer 0: GENERATES the post-(L1 product, q0, q1) state in smem, then applies
//          L1 CRX q2(cond)..q14 + L2 U wires 3..14, stores to global.
// layer 1: loads state, applies L2 CRX q2(cond)..q14, stores.
__global__ __launch_bounds__(256) void k_chain(int layer) {
    extern __shared__ float2 s[];
    __shared__ float2 A[256], Bv[32], f[16][2];
    int b = blockIdx.y, tid = threadIdx.x, chunk = blockIdx.x;
    float4* g4 = g_state4 + (size_t)b * 32768 + (size_t)chunk * 4096;
    bool dou = (layer == 0);
    bool doq2 = (chunk & 1);                          // chunk bit13 == 1
    if (layer == 0) {
        // ---- generate product state for this chunk ----
        if (tid < 32) f[tid >> 1][tid & 1] = g_U[0][b][15 - (tid >> 1)][(tid & 1) * 2];
        __syncthreads();
        {   // A: product over bits 0..7
            float2 c = f[0][tid & 1];
            #pragma unroll
            for (int j = 1; j <= 7; j++) c = cmul(c, f[j][(tid >> j) & 1]);
            A[tid] = c;
        }
        if (tid < 32) {
            // B: product over bits 8..12
            float2 c = f[8][tid & 1];
            #pragma unroll
            for (int j = 9; j <= 12; j++) c = cmul(c, f[j][(tid >> (j - 8)) & 1]);
            // F[8] over bits 13..15 with L1 q0,q1 folded; Fc = F[chunk]
            float2 F[8];
            #pragma unroll
            for (int i = 0; i < 8; i++)
                F[i] = cmul(cmul(f[13][i & 1], f[14][(i >> 1) & 1]), f[15][(i >> 2) & 1]);
            float2 cs = g_crx[0][0];                  // q0: ctrl b15 -> tgt b14
            crxmix(F[4], F[6], cs.x, cs.y); crxmix(F[5], F[7], cs.x, cs.y);
            cs = g_crx[0][1];                         // q1: ctrl b14 -> tgt b13
            crxmix(F[2], F[3], cs.x, cs.y); crxmix(F[6], F[7], cs.x, cs.y);
            Bv[tid] = cmul(c, F[chunk]);
        }
        __syncthreads();
        #pragma unroll
        for (int k = 0; k < 32; k++) {
            int j = tid + (k << 8);
            s[PD(j)] = cmul(A[j & 255], Bv[j >> 8]);
        }
    } else {
        #pragma unroll
        for (int k = 0; k < 16; k++) {
            int p = tid + (k << 8);
            float4 v = g4[p];
            s[PD(2 * p)]     = make_float2(v.x, v.y);
            s[PD(2 * p + 1)] = make_float2(v.z, v.w);
        }
    }
    __syncthreads();
    window_pass(s, tid, b, 9, dou, layer, doq2); __syncthreads();
    window_pass(s, tid, b, 6, dou, layer, false); __syncthreads();
    window_pass(s, tid, b, 3, dou, layer, false); __syncthreads();
    window_pass(s, tid, b, 0, dou, layer, false); __syncthreads();
    #pragma unroll
    for (int k = 0; k < 16; k++) {
        int p = tid + (k << 8);
        float2 lo = s[PD(2 * p)], hi = s[PD(2 * p + 1)];
        g4[p] = make_float4(lo.x, lo.y, hi.x, hi.y);
    }
}

// ------- P2: boundary gates on bits {15,14,13,0} -----------------------------
// L1 wrap q15; L2 U wires 0,1,2,15; L2 CRX q0,q1.
__global__ __launch_bounds__(256, 4) void k_boundary() {
    int b = blockIdx.y;
    int t = blockIdx.x * blockDim.x + threadIdx.x;   // 0..4095 : f4 idx (j bits 1..12)
    float4* g4 = g_state4 + (size_t)b * 32768;
    float2 r[8][2];                                  // [i=(b15<<2)|(b14<<1)|b13][b0]
    #pragma unroll
    for (int i = 0; i < 8; i++) {
        float4 v = g4[(i << 12) | t];
        r[i][0] = make_float2(v.x, v.y);
        r[i][1] = make_float2(v.z, v.w);
    }
    {   // L1 wrap q15: ctrl b0 -> tgt b15
        float2 cs = g_crx[0][15];
        #pragma unroll
        for (int i = 0; i < 4; i++) crxmix(r[i][1], r[i + 4][1], cs.x, cs.y);
    }
    {   // L2 U wire 0 (bit 15)
        const float2* gu = &g_U[1][b][0][0];
        float2 u0 = gu[0], u1 = gu[1], u2 = gu[2], u3 = gu[3];
        #pragma unroll
        for (int i = 0; i < 4; i++) {
            umix(r[i][0], r[i + 4][0], u0, u1, u2, u3);
            umix(r[i][1], r[i + 4][1], u0, u1, u2, u3);
        }
    }
    {   // L2 U wire 1 (bit 14)
        const float2* gu = &g_U[1][b][1][0];
        float2 u0 = gu[0], u1 = gu[1], u2 = gu[2], u3 = gu[3];
        #pragma unroll
        for (int i = 0; i < 8; i++)
            if (!((i >> 1) & 1)) {
                umix(r[i][0], r[i + 2][0], u0, u1, u2, u3);
                umix(r[i][1], r[i + 2][1], u0, u1, u2, u3);
            }
    }
    {   // L2 U wire 2 (bit 13)
        const float2* gu = &g_U[1][b][2][0];
        float2 u0 = gu[0], u1 = gu[1], u2 = gu[2], u3 = gu[3];
        #pragma unroll
        for (int i = 0; i < 8; i += 2) {
            umix(r[i][0], r[i + 1][0], u0, u1, u2, u3);
            umix(r[i][1], r[i + 1][1], u0, u1, u2, u3);
        }
    }
    {   // L2 U wire 15 (bit 0)
        const float2* gu = &g_U[1][b][15][0];
        float2 u0 = gu[0], u1 = gu[1], u2 = gu[2], u3 = gu[3];
        #pragma unroll
        for (int i = 0; i < 8; i++)
            umix(r[i][0], r[i][1], u0, u1, u2, u3);
    }
    {   // L2 q0: ctrl b15 -> tgt b14
        float2 cs = g_crx[1][0];
        #pragma unroll
        for (int b0 = 0; b0 < 2; b0++) {
            crxmix(r[4][b0], r[6][b0], cs.x, cs.y);
            crxmix(r[5][b0], r[7][b0], cs.x, cs.y);
        }
    }
    {   // L2 q1: ctrl b14 -> tgt b13
        float2 cs = g_crx[1][1];
        #pragma unroll
        for (int b0 = 0; b0 < 2; b0++) {
            crxmix(r[2][b0], r[3][b0], cs.x, cs.y);
            crxmix(r[6][b0], r[7][b0], cs.x, cs.y);
        }
    }
    #pragma unroll
    for (int i = 0; i < 8; i++)
        g4[(i << 12) | t] = make_float4(r[i][0].x, r[i][0].y, r[i][1].x, r[i][1].y);
}

// ------- P4: final L2 wrap CRX (q15: b0->b15) + signed |amp|^2 reduction -----
__global__ __launch_bounds__(256, 4) void k_measure() {
    int b = blockIdx.y, blk = blockIdx.x, tid = threadIdx.x;
    const float4* st4 = g_state4 + (size_t)b * 32768;
    float2 cs = g_crx[1][15];
    float sums[16];
    #pragma unroll
    for (int w = 0; w < 16; w++) sums[w] = 0.f;
    #pragma unroll
    for (int k = 0; k < 8; k++) {
        int f = blk * 2048 + tid + k * 256;          // f4 idx: j bits 1..14
        float4 lo = st4[f], hi = st4[f + 16384];
        float2 a0e = make_float2(lo.x, lo.y), a0o = make_float2(lo.z, lo.w);
        float2 a1e = make_float2(hi.x, hi.y), a1o = make_float2(hi.z, hi.w);
        crxmix(a0o, a1o, cs.x, cs.y);                // wrap only where bit0=1
        float p0e = a0e.x * a0e.x + a0e.y * a0e.y;
        float p1e = a1e.x * a1e.x + a1e.y * a1e.y;
        float p0o = a0o.x * a0o.x + a0o.y * a0o.y;
        float p1o = a1o.x * a1o.x + a1o.y * a1o.y;
        int j = f << 1;
        sums[0] += (p0e - p1e) + (p0o - p1o);        // wire 0 = bit 15
        float se = p0e + p1e, so = p0o + p1o;
        float sall = se + so;
        #pragma unroll
        for (int w = 1; w < 15; w++)
            sums[w] += ((j >> (15 - w)) & 1) ? -sall : sall;
        sums[15] += se - so;                         // wire 15 = bit 0
    }
    __shared__ float sm[256][16];
    #pragma unroll
    for (int w = 0; w < 16; w++) sm[tid][w] = sums[w];
    __syncthreads();
    if (tid < 16) {
        float v = 0.f;
        for (int i = 0; i < 256; i++) v += sm[i][tid];
        g_partial[b][blk][tid] = v;
    }
}

// ---------------- P5: FC + log_softmax --------------------------------------
__global__ void k_head(const float* __restrict__ fc_w, const float* __restrict__ fc_b,
                       float* __restrict__ out) {
    int b = blockIdx.x, lane = threadIdx.x;
    __shared__ float feats[16];
    if (lane < 16) {
        float v = 0.f;
        #pragma unroll
        for (int k = 0; k < 8; k++) v += g_partial[b][k][lane];
        feats[lane] = v;
    }
    __syncthreads();
    float logit = -1e30f;
    if (lane < NC) {
        float v = fc_b[lane];
        #pragma unroll
        for (int w = 0; w < 16; w++) v += feats[w] * fc_w[lane * 16 + w];
        logit = v;
    }
    float m = logit;
    #pragma unroll
    for (int o = 16; o; o >>= 1) m = fmaxf(m, __shfl_xor_sync(0xffffffffu, m, o));
    float e = (lane < NC) ? expf(logit - m) : 0.f;
    #pragma unroll
    for (int o = 16; o; o >>= 1) e += __shfl_xor_sync(0xffffffffu, e, o);
    float lse = m + logf(e);
    if (lane < NC) out[b * NC + lane] = logit - lse;
}

extern "C" void kernel_launch(void* const* d_in, const int* in_sizes, int n_in,
                              void* d_out, int out_size) {
    const float* x    = (const float*)d_in[0];
    const float* w0   = (const float*)d_in[1];
    const float* x0   = (const float*)d_in[2];
    const float* w1   = (const float*)d_in[3];
    const float* x1   = (const float*)d_in[4];
    const float* fc_w = (const float*)d_in[5];
    const float* fc_b = (const float*)d_in[6];
    float* out = (float*)d_out;

    cudaFuncSetAttribute(k_chain, cudaFuncAttributeMaxDynamicSharedMemorySize, SMEM_BYTES);

    k_prep<<<8, 256>>>(x, w0, x0, w1, x1);
    k_chain<<<dim3(8, BATCH), 256, SMEM_BYTES>>>(0);
    k_boundary<<<dim3(16, BATCH), 256>>>();
    k_chain<<<dim3(8, BATCH), 256, SMEM_BYTES>>>(1);
    k_measure<<<dim3(8, BATCH), 256>>>();
    k_head<<<BATCH, 32>>>(fc_w, fc_b, out);
}